// round 5
// baseline (speedup 1.0000x reference)
#include <cuda_runtime.h>

// RNN_26938034880941: vanilla tanh RNN  B=4096, S=512, I=1, H=16, O=1
// Round 5: R4's lean step + 2 interleaved chains per 16-lane group.
//   16 lanes per batch-pair; lane owns hidden unit j for batches A and B.
//   4 batches/warp, 16 batches per 128-thread block, grid = 256 blocks.
//   Chain B's instructions issue inside chain A's latency shadow.
// Bank-exact smem: each group owns a 128B region; group g places row A at
//   +g*64 and row B at +(g^1)*64, so every LDS/STS is conflict-free across
//   the warp's two half-groups.
// tanh.approx for steps 0..447, exact ex2/rcp for last 64 (error decays).
// W_hh registers shared by both chains (same j). x via broadcast LDG.128
// quads with depth-2 register prefetch per chain.

#define TWO_LOG2E 2.88539008177792681472f  // 2*log2(e)

__device__ __forceinline__ unsigned long long pack2(float a, float b) {
    unsigned long long r;
    asm("mov.b64 %0, {%1, %2};" : "=l"(r) : "f"(a), "f"(b));
    return r;
}
__device__ __forceinline__ unsigned long long fma2(unsigned long long a,
                                                   unsigned long long b,
                                                   unsigned long long c) {
    unsigned long long d;
    asm("fma.rn.f32x2 %0, %1, %2, %3;" : "=l"(d) : "l"(a), "l"(b), "l"(c));
    return d;
}
__device__ __forceinline__ unsigned long long mul2(unsigned long long a,
                                                   unsigned long long b) {
    unsigned long long d;
    asm("mul.rn.f32x2 %0, %1, %2;" : "=l"(d) : "l"(a), "l"(b));
    return d;
}
__device__ __forceinline__ unsigned long long add2(unsigned long long a,
                                                   unsigned long long b) {
    unsigned long long d;
    asm("add.rn.f32x2 %0, %1, %2;" : "=l"(d) : "l"(a), "l"(b));
    return d;
}
// Ordered smem ops (converged warp; in-warp LSU program order; memory clobber
// stops compiler reordering).
__device__ __forceinline__ void lds_v2u64(unsigned long long& a,
                                          unsigned long long& b, unsigned sa) {
    asm volatile("ld.shared.v2.b64 {%0, %1}, [%2];"
                 : "=l"(a), "=l"(b) : "r"(sa) : "memory");
}
__device__ __forceinline__ void sts_f32(unsigned sa, float v) {
    asm volatile("st.shared.f32 [%0], %1;" :: "r"(sa), "f"(v) : "memory");
}

__global__ void __launch_bounds__(128)
rnn_kernel(const float* __restrict__ x,     // [4096,512,1]
           const float* __restrict__ Wih,   // [16,1]
           const float* __restrict__ Whh,   // [16,16]
           const float* __restrict__ bih,   // [16]
           const float* __restrict__ bhh,   // [16]
           const float* __restrict__ Wfc,   // [1,16]
           const float* __restrict__ bfc,   // [1]
           float* __restrict__ out)         // [4096,1]
{
    // 8 groups per block, 128B h-region per group (rows A and B, 64B each).
    __shared__ __align__(128) float hbuf[8 * 32];

    const int tid  = threadIdx.x;
    const int lane = tid & 31;
    const int warp = tid >> 5;
    const int g    = lane >> 4;   // half-group within warp (0/1)
    const int j    = lane & 15;   // hidden unit owned by this thread
    const int gid  = warp * 2 + g;            // group in block (0..7)
    const int batchA = blockIdx.x * 16 + gid * 2;
    const int batchB = batchA + 1;
    const float* xrowA = x + (size_t)batchA * 512;
    const float* xrowB = x + (size_t)batchB * 512;

    // ---- shared weights: row j of W_hh packed into f32x2 pairs ----
    const float4 w0 = *(const float4*)(Whh + j * 16 + 0);
    const float4 w1 = *(const float4*)(Whh + j * 16 + 4);
    const float4 w2 = *(const float4*)(Whh + j * 16 + 8);
    const float4 w3 = *(const float4*)(Whh + j * 16 + 12);
    unsigned long long Wp[8];
    Wp[0] = pack2(w0.x, w0.y);  Wp[1] = pack2(w0.z, w0.w);
    Wp[2] = pack2(w1.x, w1.y);  Wp[3] = pack2(w1.z, w1.w);
    Wp[4] = pack2(w2.x, w2.y);  Wp[5] = pack2(w2.z, w2.w);
    Wp[6] = pack2(w3.x, w3.y);  Wp[7] = pack2(w3.z, w3.w);
    const float wihj = Wih[j];
    const float bj   = bih[j] + bhh[j];

    // ---- bank-exact row addresses ----
    // group region = gid*128; row A at +g*64, row B at +(g^1)*64.
    const unsigned smem0 = (unsigned)__cvta_generic_to_shared(hbuf);
    const unsigned base  = smem0 + (unsigned)(gid * 128);
    const unsigned rowA  = base + (unsigned)(g << 6);
    const unsigned rowB  = base + (unsigned)((g ^ 1) << 6);
    const unsigned stA   = rowA + (unsigned)(j * 4);
    const unsigned stB   = rowB + (unsigned)(j * 4);

    // ---- h0 = 0 ----
    sts_f32(stA, 0.0f);
    sts_f32(stB, 0.0f);
    __syncwarp();   // one-time ordering of init stores

    float hA = 0.0f, hB = 0.0f;

    // ---- x quad prefetch (4 steps per float4, depth 2, both chains) ----
    float4 curA = *(const float4*)(xrowA + 0);
    float4 curB = *(const float4*)(xrowB + 0);
    float4 nxtA = *(const float4*)(xrowA + 4);
    float4 nxtB = *(const float4*)(xrowB + 4);

    // Interleaved dot front-ends for both chains.
#define DOT2(QXA, QXB, ZA, ZB)                                          \
        unsigned long long A0, A1, A2, A3, A4, A5, A6, A7;              \
        unsigned long long B0, B1, B2, B3, B4, B5, B6, B7;              \
        lds_v2u64(A0, A1, rowA + 0);                                    \
        lds_v2u64(A2, A3, rowA + 16);                                   \
        lds_v2u64(A4, A5, rowA + 32);                                   \
        lds_v2u64(A6, A7, rowA + 48);                                   \
        lds_v2u64(B0, B1, rowB + 0);                                    \
        lds_v2u64(B2, B3, rowB + 16);                                   \
        lds_v2u64(B4, B5, rowB + 32);                                   \
        lds_v2u64(B6, B7, rowB + 48);                                   \
        unsigned long long a0 = mul2(A0, Wp[0]);                        \
        unsigned long long a1 = mul2(A1, Wp[1]);                        \
        unsigned long long b0 = mul2(B0, Wp[0]);                        \
        unsigned long long b1 = mul2(B1, Wp[1]);                        \
        a0 = fma2(A2, Wp[2], a0);                                       \
        a1 = fma2(A3, Wp[3], a1);                                       \
        b0 = fma2(B2, Wp[2], b0);                                       \
        b1 = fma2(B3, Wp[3], b1);                                       \
        a0 = fma2(A4, Wp[4], a0);                                       \
        a1 = fma2(A5, Wp[5], a1);                                       \
        b0 = fma2(B4, Wp[4], b0);                                       \
        b1 = fma2(B5, Wp[5], b1);                                       \
        a0 = fma2(A6, Wp[6], a0);                                       \
        a1 = fma2(A7, Wp[7], a1);                                       \
        b0 = fma2(B6, Wp[6], b0);                                       \
        b1 = fma2(B7, Wp[7], b1);                                       \
        a0 = add2(a0, a1);                                              \
        b0 = add2(b0, b1);                                              \
        float zAlo, zAhi, zBlo, zBhi;                                   \
        asm("mov.b64 {%0, %1}, %2;" : "=f"(zAlo), "=f"(zAhi) : "l"(a0));\
        asm("mov.b64 {%0, %1}, %2;" : "=f"(zBlo), "=f"(zBhi) : "l"(b0));\
        float ZA = ((QXA) + zAlo) + zAhi;                               \
        float ZB = ((QXB) + zBlo) + zBhi;

    // Fast macro-step: both chains, tanh.approx
#define STEP2_FAST(QXA, QXB)                                            \
    do {                                                                \
        DOT2(QXA, QXB, zA, zB)                                          \
        asm("tanh.approx.f32 %0, %1;" : "=f"(hA) : "f"(zA));            \
        asm("tanh.approx.f32 %0, %1;" : "=f"(hB) : "f"(zB));            \
        sts_f32(stA, hA);                                               \
        sts_f32(stB, hB);                                               \
    } while (0)

    // Exact macro-step: both chains, h = 1 - 2/(ex2(c*z)+1)
#define STEP2_EXACT(QXA, QXB)                                           \
    do {                                                                \
        DOT2(QXA, QXB, zA, zB)                                          \
        float qA = zA * TWO_LOG2E;                                      \
        float qB = zB * TWO_LOG2E;                                      \
        float eA, eB, rA, rB;                                           \
        asm("ex2.approx.f32 %0, %1;" : "=f"(eA) : "f"(qA));             \
        asm("ex2.approx.f32 %0, %1;" : "=f"(eB) : "f"(qB));             \
        float dA = eA + 1.0f;                                           \
        float dB = eB + 1.0f;                                           \
        asm("rcp.approx.f32 %0, %1;" : "=f"(rA) : "f"(dA));             \
        asm("rcp.approx.f32 %0, %1;" : "=f"(rB) : "f"(dB));             \
        hA = fmaf(-2.0f, rA, 1.0f);                                     \
        hB = fmaf(-2.0f, rB, 1.0f);                                     \
        sts_f32(stA, hA);                                               \
        sts_f32(stB, hB);                                               \
    } while (0)

    // ---- phase 1: steps 0..447 fast (112 quads) ----
#pragma unroll 1
    for (int t4 = 0; t4 < 112; ++t4) {
        const int nidx = t4 + 2;  // max 113 < 128
        float4 tmpA = *(const float4*)(xrowA + nidx * 4);
        float4 tmpB = *(const float4*)(xrowB + nidx * 4);
        float qA0 = fmaf(curA.x, wihj, bj), qB0 = fmaf(curB.x, wihj, bj);
        float qA1 = fmaf(curA.y, wihj, bj), qB1 = fmaf(curB.y, wihj, bj);
        float qA2 = fmaf(curA.z, wihj, bj), qB2 = fmaf(curB.z, wihj, bj);
        float qA3 = fmaf(curA.w, wihj, bj), qB3 = fmaf(curB.w, wihj, bj);
        STEP2_FAST(qA0, qB0);
        STEP2_FAST(qA1, qB1);
        STEP2_FAST(qA2, qB2);
        STEP2_FAST(qA3, qB3);
        curA = nxtA;  nxtA = tmpA;
        curB = nxtB;  nxtB = tmpB;
    }

    // ---- phase 2: steps 448..511 exact (16 quads) ----
#pragma unroll 1
    for (int t4 = 112; t4 < 128; ++t4) {
        const int nidx = (t4 + 2 < 128) ? (t4 + 2) : 127;
        float4 tmpA = *(const float4*)(xrowA + nidx * 4);
        float4 tmpB = *(const float4*)(xrowB + nidx * 4);
        float qA0 = fmaf(curA.x, wihj, bj), qB0 = fmaf(curB.x, wihj, bj);
        float qA1 = fmaf(curA.y, wihj, bj), qB1 = fmaf(curB.y, wihj, bj);
        float qA2 = fmaf(curA.z, wihj, bj), qB2 = fmaf(curB.z, wihj, bj);
        float qA3 = fmaf(curA.w, wihj, bj), qB3 = fmaf(curB.w, wihj, bj);
        STEP2_EXACT(qA0, qB0);
        STEP2_EXACT(qA1, qB1);
        STEP2_EXACT(qA2, qB2);
        STEP2_EXACT(qA3, qB3);
        curA = nxtA;  nxtA = tmpA;
        curB = nxtB;  nxtB = tmpB;
    }
#undef STEP2_FAST
#undef STEP2_EXACT
#undef DOT2

    // ---- epilogue: out[b] = sum_j h_j * Wfc[j] + bfc, both chains ----
    const float wfcj = Wfc[j];
    float vA = hA * wfcj;
    float vB = hB * wfcj;
#pragma unroll
    for (int msk = 8; msk >= 1; msk >>= 1) {
        vA += __shfl_xor_sync(0xffffffffu, vA, msk);
        vB += __shfl_xor_sync(0xffffffffu, vB, msk);
    }
    if (j == 0) {
        const float bias = bfc[0];
        out[batchA] = vA + bias;
        out[batchB] = vB + bias;
    }
}

extern "C" void kernel_launch(void* const* d_in, const int* in_sizes, int n_in,
                              void* d_out, int out_size) {
    const float* x   = (const float*)d_in[0];
    const float* Wih = (const float*)d_in[1];
    const float* Whh = (const float*)d_in[2];
    const float* bih = (const float*)d_in[3];
    const float* bhh = (const float*)d_in[4];
    const float* Wfc = (const float*)d_in[5];
    const float* bfc = (const float*)d_in[6];
    float* out = (float*)d_out;

    // 4096 batches / 16 per block = 256 blocks, 128 threads each
    rnn_kernel<<<256, 128>>>(x, Wih, Whh, bih, bhh, Wfc, bfc, out);
}

// round 6
// speedup vs baseline: 1.2378x; 1.2378x over previous
#include <cuda_runtime.h>

// RNN_26938034880941: vanilla tanh RNN  B=4096, S=512, I=1, H=16, O=1
// Round 6: lean single-chain step (R4 skeleton; ILP attempts abandoned —
// dur = 512*T_step, warp count irrelevant, in-order issue kills interleave).
//  - qx folded into accumulator init (off critical path)
//  - tail: alias-unpack + ONE FADD (was mov+2 FADD)
//  - tanh.approx for steps 0..447, exact ex2/rcp for last 64
//  - x via LDG.128 quads, depth-2 register prefetch; no x smem
// 16 lanes/batch, 2 batches/warp, 512 blocks x 128 threads.

#define TWO_LOG2E 2.88539008177792681472f  // 2*log2(e)

__device__ __forceinline__ unsigned long long pack2(float a, float b) {
    unsigned long long r;
    asm("mov.b64 %0, {%1, %2};" : "=l"(r) : "f"(a), "f"(b));
    return r;
}
__device__ __forceinline__ unsigned long long fma2(unsigned long long a,
                                                   unsigned long long b,
                                                   unsigned long long c) {
    unsigned long long d;
    asm("fma.rn.f32x2 %0, %1, %2, %3;" : "=l"(d) : "l"(a), "l"(b), "l"(c));
    return d;
}
__device__ __forceinline__ unsigned long long add2(unsigned long long a,
                                                   unsigned long long b) {
    unsigned long long d;
    asm("add.rn.f32x2 %0, %1, %2;" : "=l"(d) : "l"(a), "l"(b));
    return d;
}
// Ordered smem ops (converged warp; in-warp LSU program order; memory clobber
// stops compiler reordering).
__device__ __forceinline__ void lds_v2u64(unsigned long long& a,
                                          unsigned long long& b, unsigned sa) {
    asm volatile("ld.shared.v2.b64 {%0, %1}, [%2];"
                 : "=l"(a), "=l"(b) : "r"(sa) : "memory");
}
__device__ __forceinline__ void sts_f32(unsigned sa, float v) {
    asm volatile("st.shared.f32 [%0], %1;" :: "r"(sa), "f"(v) : "memory");
}

__global__ void __launch_bounds__(128)
rnn_kernel(const float* __restrict__ x,     // [4096,512,1]
           const float* __restrict__ Wih,   // [16,1]
           const float* __restrict__ Whh,   // [16,16]
           const float* __restrict__ bih,   // [16]
           const float* __restrict__ bhh,   // [16]
           const float* __restrict__ Wfc,   // [1,16]
           const float* __restrict__ bfc,   // [1]
           float* __restrict__ out)         // [4096,1]
{
    // 8 batches per block; h-rows 64B apart -> the warp's two groups use
    // disjoint bank halves.
    __shared__ __align__(16) float hbuf[8][16];

    const int tid  = threadIdx.x;
    const int lane = tid & 31;
    const int warp = tid >> 5;
    const int g    = lane >> 4;   // group within warp (0/1)
    const int j    = lane & 15;   // hidden unit owned by this thread
    const int bib  = warp * 2 + g;            // batch within block (0..7)
    const int batch = blockIdx.x * 8 + bib;   // global batch
    const float* xrow = x + (size_t)batch * 512;

    // ---- plain weights: row j of W_hh packed into f32x2 pairs ----
    const float4 w0 = *(const float4*)(Whh + j * 16 + 0);
    const float4 w1 = *(const float4*)(Whh + j * 16 + 4);
    const float4 w2 = *(const float4*)(Whh + j * 16 + 8);
    const float4 w3 = *(const float4*)(Whh + j * 16 + 12);
    unsigned long long Wp[8];
    Wp[0] = pack2(w0.x, w0.y);  Wp[1] = pack2(w0.z, w0.w);
    Wp[2] = pack2(w1.x, w1.y);  Wp[3] = pack2(w1.z, w1.w);
    Wp[4] = pack2(w2.x, w2.y);  Wp[5] = pack2(w2.z, w2.w);
    Wp[6] = pack2(w3.x, w3.y);  Wp[7] = pack2(w3.z, w3.w);
    const float wihj = Wih[j];
    const float bj   = bih[j] + bhh[j];

    const unsigned hrow_sa = (unsigned)__cvta_generic_to_shared(&hbuf[bib][0]);
    const unsigned hst_sa  = hrow_sa + (unsigned)(j * 4);

    // ---- h0 = 0 ----
    hbuf[bib][j] = 0.0f;
    __syncwarp();   // one-time: order init stores before first asm LDS

    float hcur = 0.0f;

    // ---- x quad prefetch pipeline (4 steps per float4, depth 2) ----
    float4 cur = *(const float4*)(xrow + 0);
    float4 nxt = *(const float4*)(xrow + 4);

    // Dot front-end. qx (x-bias) is folded into accumulator a1's init so the
    // post-reduction tail is a single FADD: z = zlo + zhi.
#define DOT_Z(QX, ZOUT)                                                 \
        unsigned long long qxp = pack2((QX), 0.0f);                     \
        unsigned long long h0, h1, h2, h3, h4, h5, h6, h7;              \
        lds_v2u64(h0, h1, hrow_sa + 0);                                 \
        lds_v2u64(h2, h3, hrow_sa + 16);                                \
        lds_v2u64(h4, h5, hrow_sa + 32);                                \
        lds_v2u64(h6, h7, hrow_sa + 48);                                \
        unsigned long long a0 = mul2_init(h0, Wp[0]);                   \
        unsigned long long a1 = fma2(h1, Wp[1], qxp);                   \
        a0 = fma2(h2, Wp[2], a0);                                       \
        a1 = fma2(h3, Wp[3], a1);                                       \
        a0 = fma2(h4, Wp[4], a0);                                       \
        a1 = fma2(h5, Wp[5], a1);                                       \
        a0 = fma2(h6, Wp[6], a0);                                       \
        a1 = fma2(h7, Wp[7], a1);                                       \
        a0 = add2(a0, a1);                                              \
        float zlo, zhi;                                                 \
        asm("mov.b64 {%0, %1}, %2;" : "=f"(zlo), "=f"(zhi) : "l"(a0));  \
        float ZOUT = zlo + zhi;

    // Fast step: h = tanh.approx(z)
#define STEP_FAST(QX)                                                   \
    do {                                                                \
        DOT_Z(QX, z)                                                    \
        asm("tanh.approx.f32 %0, %1;" : "=f"(hcur) : "f"(z));           \
        sts_f32(hst_sa, hcur);                                          \
    } while (0)

    // Exact step: h = 1 - 2/(ex2(2*log2e*z)+1)
#define STEP_EXACT(QX)                                                  \
    do {                                                                \
        DOT_Z(QX, z)                                                    \
        float q = z * TWO_LOG2E;                                        \
        float e;                                                        \
        asm("ex2.approx.f32 %0, %1;" : "=f"(e) : "f"(q));               \
        float dd = e + 1.0f;                                            \
        float r;                                                        \
        asm("rcp.approx.f32 %0, %1;" : "=f"(r) : "f"(dd));              \
        hcur = fmaf(-2.0f, r, 1.0f);                                    \
        sts_f32(hst_sa, hcur);                                          \
    } while (0)

// mul2 used for a0 init (no addend available; keep as plain mul)
#define mul2_init(A, B) ({                                              \
        unsigned long long _d;                                          \
        asm("mul.rn.f32x2 %0, %1, %2;" : "=l"(_d) : "l"(A), "l"(B));    \
        _d; })

    // ---- phase 1: steps 0..447 fast (112 quads) ----
#pragma unroll 2
    for (int t4 = 0; t4 < 112; ++t4) {
        const int nidx = t4 + 2;  // max 113 < 128
        float4 tmp = *(const float4*)(xrow + nidx * 4);
        float qx0 = fmaf(cur.x, wihj, bj);
        float qx1 = fmaf(cur.y, wihj, bj);
        float qx2 = fmaf(cur.z, wihj, bj);
        float qx3 = fmaf(cur.w, wihj, bj);
        STEP_FAST(qx0);
        STEP_FAST(qx1);
        STEP_FAST(qx2);
        STEP_FAST(qx3);
        cur = nxt;
        nxt = tmp;
    }

    // ---- phase 2: steps 448..511 exact (16 quads) ----
#pragma unroll 2
    for (int t4 = 112; t4 < 128; ++t4) {
        const int nidx = (t4 + 2 < 128) ? (t4 + 2) : 127;
        float4 tmp = *(const float4*)(xrow + nidx * 4);
        float qx0 = fmaf(cur.x, wihj, bj);
        float qx1 = fmaf(cur.y, wihj, bj);
        float qx2 = fmaf(cur.z, wihj, bj);
        float qx3 = fmaf(cur.w, wihj, bj);
        STEP_EXACT(qx0);
        STEP_EXACT(qx1);
        STEP_EXACT(qx2);
        STEP_EXACT(qx3);
        cur = nxt;
        nxt = tmp;
    }
#undef STEP_FAST
#undef STEP_EXACT
#undef DOT_Z
#undef mul2_init

    // ---- epilogue: out[b] = sum_j h_j * Wfc[j] + bfc ----
    float v = hcur * Wfc[j];
#pragma unroll
    for (int msk = 8; msk >= 1; msk >>= 1)
        v += __shfl_xor_sync(0xffffffffu, v, msk);
    if (j == 0)
        out[batch] = v + bfc[0];
}

extern "C" void kernel_launch(void* const* d_in, const int* in_sizes, int n_in,
                              void* d_out, int out_size) {
    const float* x   = (const float*)d_in[0];
    const float* Wih = (const float*)d_in[1];
    const float* Whh = (const float*)d_in[2];
    const float* bih = (const float*)d_in[3];
    const float* bhh = (const float*)d_in[4];
    const float* Wfc = (const float*)d_in[5];
    const float* bfc = (const float*)d_in[6];
    float* out = (float*)d_out;

    rnn_kernel<<<512, 128>>>(x, Wih, Whh, bih, bhh, Wfc, bfc, out);
}